// round 4
// baseline (speedup 1.0000x reference)
#include <cuda_runtime.h>
#include <stdint.h>

// Problem constants
#define Bc 32
#define Nc 512
#define Gc 64
#define Tc 16
#define Dc 256
#define NTGT (Bc * Gc)          // 2048 goal rows
#define EMAX 500000

static __device__ __constant__ float NEGV = -1.0e10f;

// Scratch (static __device__ per harness rules)
__device__ float g_V[NTGT * Dc];       // V[g][d] = W @ goal_type[g]   (2 MB)
__device__ int   g_cnt[NTGT];
__device__ int   g_off[NTGT];
__device__ int   g_base[NTGT];
__device__ int   g_perm[EMAX];         // edge ids grouped by tgt (2 MB)
__device__ int   g_mask_kind;          // 0=u8, 1=i32, 2=f32

// ---------------------------------------------------------------------------
// Kernel 0: classify tree_mask storage (first 4096 words safe for all dtypes)
// ---------------------------------------------------------------------------
__global__ void detect_mask_kind_kernel(const uint32_t* __restrict__ mw) {
    __shared__ int ok_i32, ok_f32;
    if (threadIdx.x == 0) { ok_i32 = 1; ok_f32 = 1; }
    __syncthreads();
    int li = 1, lf = 1;
    for (int i = threadIdx.x; i < 4096; i += blockDim.x) {
        uint32_t w = mw[i];
        if (!(w == 0u || w == 1u)) li = 0;
        if (!(w == 0u || w == 0x3F800000u)) lf = 0;
    }
    if (!li) ok_i32 = 0;   // benign race: all writers store 0
    if (!lf) ok_f32 = 0;
    __syncthreads();
    if (threadIdx.x == 0) g_mask_kind = ok_i32 ? 1 : (ok_f32 ? 2 : 0);
}

// ---------------------------------------------------------------------------
// Kernel 1: V[g][d] = sum_f W[d][f] * goal_type[g][f]
// ---------------------------------------------------------------------------
__global__ void compute_V_kernel(const float* __restrict__ goal,
                                 const float* __restrict__ W) {
    __shared__ float sg[32][Dc];           // 32 KB
    const int g0 = blockIdx.x * 32;
    for (int i = threadIdx.x; i < 32 * Dc; i += blockDim.x) {
        int g = i >> 8, f = i & 255;
        sg[g][f] = goal[(size_t)(g0 + g) * (Tc * Dc) + f];
    }
    __syncthreads();
    const int d = threadIdx.x;
    float acc[32];
#pragma unroll
    for (int g = 0; g < 32; g++) acc[g] = 0.f;
    const float4* Wrow = reinterpret_cast<const float4*>(W + (size_t)d * Dc);
#pragma unroll 4
    for (int f4 = 0; f4 < Dc / 4; f4++) {
        float4 w = Wrow[f4];
#pragma unroll
        for (int g = 0; g < 32; g++) {
            float4 s = reinterpret_cast<const float4*>(sg[g])[f4];  // broadcast
            acc[g] += w.x * s.x + w.y * s.y + w.z * s.z + w.w * s.w;
        }
    }
#pragma unroll
    for (int g = 0; g < 32; g++)
        g_V[(size_t)(g0 + g) * Dc + d] = acc[g];
}

// ---------------------------------------------------------------------------
// Edge bucketing: zero -> histogram(tgt) -> scan -> scatter(perm)
// ---------------------------------------------------------------------------
__global__ void zero_cnt_kernel() {
    int i = blockIdx.x * blockDim.x + threadIdx.x;
    if (i < NTGT) g_cnt[i] = 0;
}

__global__ void hist_kernel(const int* __restrict__ ei, int E) {
    int i = blockIdx.x * blockDim.x + threadIdx.x;
    if (i < E) atomicAdd(&g_cnt[ei[E + i]], 1);
}

// single block, 1024 threads, 2 buckets each: exclusive scan of g_cnt
__global__ void scan_kernel() {
    __shared__ int wsum[32];
    const int t = threadIdx.x, lane = t & 31, w = t >> 5;
    int a = g_cnt[2 * t], b = g_cnt[2 * t + 1];
    int s = a + b;
    int v = s;
#pragma unroll
    for (int o = 1; o < 32; o <<= 1) {
        int u = __shfl_up_sync(0xffffffffu, v, o);
        if (lane >= o) v += u;
    }
    if (lane == 31) wsum[w] = v;
    __syncthreads();
    if (w == 0) {
        int x = wsum[lane];
#pragma unroll
        for (int o = 1; o < 32; o <<= 1) {
            int u = __shfl_up_sync(0xffffffffu, x, o);
            if (lane >= o) x += u;
        }
        wsum[lane] = x;
    }
    __syncthreads();
    int excl = v - s + (w ? wsum[w - 1] : 0);
    g_base[2 * t] = excl;     g_off[2 * t] = excl;
    g_base[2 * t + 1] = excl + a; g_off[2 * t + 1] = excl + a;
}

__global__ void scatter_kernel(const int* __restrict__ ei, int E) {
    int i = blockIdx.x * blockDim.x + threadIdx.x;
    if (i < E) {
        int t = ei[E + i];
        int p = atomicAdd(&g_off[t], 1);
        g_perm[p] = i;
    }
}

// ---------------------------------------------------------------------------
// Kernel 2: lemma_preds[e] = dot(scope_type[src[e]], V[tgt[e]]) + bias.
// One block per tgt bucket; V[tgt] hoisted into registers (per-lane float4x2);
// warp-per-edge streams the scope row (the only L2 traffic: 500k x 1KB).
// ---------------------------------------------------------------------------
__global__ void edge_grouped_kernel(const float* __restrict__ scope,
                                    const int* __restrict__ ei,
                                    const float* __restrict__ bias,
                                    float* __restrict__ out, int E) {
    __shared__ float sV[Dc];
    const int tgt = blockIdx.x;
    for (int i = threadIdx.x; i < Dc; i += blockDim.x)
        sV[i] = g_V[(size_t)tgt * Dc + i];
    __syncthreads();

    const int w = threadIdx.x >> 5, lane = threadIdx.x & 31;
    const float4* v4 = reinterpret_cast<const float4*>(sV);
    const float4 v0 = v4[lane], v1 = v4[lane + 32];
    const float b0 = __ldg(bias);
    const int base = g_base[tgt], cnt = g_cnt[tgt];

    for (int i = w; i < cnt; i += 8) {
        const int e = g_perm[base + i];
        const int src = ei[e];
        const float4* s = reinterpret_cast<const float4*>(scope + (size_t)src * (Tc * Dc));
        float4 s0 = s[lane], s1 = s[lane + 32];
        float p = s0.x * v0.x + s0.y * v0.y + s0.z * v0.z + s0.w * v0.w
                + s1.x * v1.x + s1.y * v1.y + s1.z * v1.z + s1.w * v1.w;
#pragma unroll
        for (int o = 16; o; o >>= 1) p += __shfl_xor_sync(0xffffffffu, p, o);
        if (lane == 0) out[e] = p + b0;
    }
}

// ---------------------------------------------------------------------------
// Kernel 3: lm_preds — shared-memory micro-GEMM, no inner-loop shuffles.
// Block = (32-n tile, batch b). Scope tile staged TRANSPOSED + XOR-swizzled
// (conflict-free loads AND stores). Mask rows in groups of MG=4 with
// broadcast LDS.128. Warp q owns d-chunk [32q,32q+32); partials reduced
// once through smem per group.
// ---------------------------------------------------------------------------
#define NT 32
#define MG 4
__global__ void lm_kernel2(const float* __restrict__ scope,
                           const int* __restrict__ lm_idx,
                           const int* __restrict__ bpts,
                           const void* __restrict__ tree_mask,
                           float* __restrict__ out, int M) {
    __shared__ float sS[Dc * NT];          // 32 KB, [d][n^sw(d)]
    __shared__ float sM[Dc * MG];          // 4 KB, [d][mi]
    __shared__ float sP[8 * MG * NT];      // 4 KB, [q][mi][n]
    __shared__ int   s_list[1024];         // 4 KB — a batch may own all of M
    __shared__ int   s_cnt;
    __shared__ unsigned s_tm;

    const int b = blockIdx.y;
    const int n0 = blockIdx.x * NT;
    const int tid = threadIdx.x, lane = tid & 31, q = tid >> 5;

    if (tid == 0) s_cnt = 0;
    __syncthreads();

    // gather this batch's m-list
    for (int m = tid; m < M; m += 256)
        if (bpts[m] == b) {
            int p = atomicAdd(&s_cnt, 1);
            s_list[p] = m;
        }

    // tree-mask bits for the 32 n's of this tile
    if (q == 0) {
        const int n = n0 + lane;
        const int kind = g_mask_kind;
        bool mk;
        if (kind == 0)      mk = ((const uint8_t*)tree_mask)[b * Nc + n] != 0;
        else if (kind == 1) mk = ((const int*)tree_mask)[b * Nc + n] != 0;
        else                mk = ((const float*)tree_mask)[b * Nc + n] != 0.f;
        unsigned bal = __ballot_sync(0xffffffffu, mk);
        if (lane == 0) s_tm = bal;
    }

    // stage scope tile transposed + swizzled: element (d,n) at [d*NT + (n^((d>>2)&31))]
    for (int idx = tid; idx < NT * (Dc / 4); idx += 256) {
        const int n = idx >> 6, d4 = idx & 63;
        float4 v = *reinterpret_cast<const float4*>(
            scope + (size_t)(b * Nc + n0 + n) * (Tc * Dc) + d4 * 4);
        const int d = d4 * 4;
        const int sw = d4 & 31;
        sS[(d + 0) * NT + (n ^ sw)] = v.x;
        sS[(d + 1) * NT + (n ^ sw)] = v.y;
        sS[(d + 2) * NT + (n ^ sw)] = v.z;
        sS[(d + 3) * NT + (n ^ sw)] = v.w;
    }
    __syncthreads();

    const int cnt = (s_cnt < M) ? s_cnt : M;
    const unsigned tmbits = s_tm;

    for (int i0 = 0; i0 < cnt; i0 += MG) {
        const int g = (cnt - i0 < MG) ? (cnt - i0) : MG;
        // stage mask rows [d][mi] (coalesced global reads)
        for (int idx = tid; idx < g * Dc; idx += 256) {
            const int mi = idx >> 8, d = idx & 255;
            sM[d * MG + mi] = scope[(size_t)lm_idx[s_list[i0 + mi]] * Dc + d];
        }
        __syncthreads();

        float acc0 = 0.f, acc1 = 0.f, acc2 = 0.f, acc3 = 0.f;
#pragma unroll
        for (int i = 0; i < 32; i++) {
            const int d = q * 32 + i;
            const float sval = sS[d * NT + (lane ^ ((d >> 2) & 31))];
            const float4 mv = *reinterpret_cast<const float4*>(sM + d * MG);
            acc0 += sval * mv.x;
            acc1 += sval * mv.y;
            acc2 += sval * mv.z;
            acc3 += sval * mv.w;
        }
        sP[(q * MG + 0) * NT + lane] = acc0;
        sP[(q * MG + 1) * NT + lane] = acc1;
        sP[(q * MG + 2) * NT + lane] = acc2;
        sP[(q * MG + 3) * NT + lane] = acc3;
        __syncthreads();

        if (tid < 32 * g) {
            const int n = lane, mi = q;
            float sum = 0.f;
#pragma unroll
            for (int qq = 0; qq < 8; qq++)
                sum += sP[(qq * MG + mi) * NT + n];
            const int m = s_list[i0 + mi];
            out[(size_t)m * Nc + n0 + n] = ((tmbits >> n) & 1u) ? sum : NEGV;
        }
        __syncthreads();
    }
}

// ---------------------------------------------------------------------------
// Launcher. Inputs: scope, goal, W, bias, edge_index, lm_mask_idx, batch_pts,
// tree_mask. Output: [lemma_preds (E) | lm_preds (M*Nc)] float32.
// ---------------------------------------------------------------------------
extern "C" void kernel_launch(void* const* d_in, const int* in_sizes, int n_in,
                              void* d_out, int out_size) {
    const float* scope = (const float*)d_in[0];
    const float* goal  = (const float*)d_in[1];
    const float* W     = (const float*)d_in[2];
    const float* bias  = (const float*)d_in[3];
    const int*   ei    = (const int*)d_in[4];
    const int*   lmidx = (const int*)d_in[5];
    const int*   bpts  = (const int*)d_in[6];
    const void*  tmask = d_in[7];
    float* out = (float*)d_out;

    const int E = in_sizes[4] / 2;
    const int M = in_sizes[5];

    detect_mask_kind_kernel<<<1, 256>>>((const uint32_t*)tmask);
    compute_V_kernel<<<(Bc * Gc) / 32, 256>>>(goal, W);

    zero_cnt_kernel<<<(NTGT + 255) / 256, 256>>>();
    hist_kernel<<<(E + 255) / 256, 256>>>(ei, E);
    scan_kernel<<<1, 1024>>>();
    scatter_kernel<<<(E + 255) / 256, 256>>>(ei, E);

    edge_grouped_kernel<<<NTGT, 256>>>(scope, ei, bias, out, E);
    lm_kernel2<<<dim3(Nc / NT, Bc), 256>>>(scope, lmidx, bpts, tmask,
                                           out + E, M);
}

// round 6
// speedup vs baseline: 1.2471x; 1.2471x over previous
#include <cuda_runtime.h>
#include <stdint.h>

// Problem constants
#define Bc 32
#define Nc 512
#define Gc 64
#define Tc 16
#define Dc 256
#define NTGT (Bc * Gc)          // 2048 goal rows
#define EMAX 500000
#define NB 128                  // bucketing blocks

static __device__ __constant__ float NEGV = -1.0e10f;

// Scratch (static __device__ per harness rules)
__device__ float g_V[NTGT * Dc];       // V[g][d] = W @ goal_type[g]   (2 MB)
__device__ int   g_cnt[NTGT];
__device__ int   g_base[NTGT];
__device__ int   g_mat[NB * NTGT];     // per-(block,tgt) counts -> prefixes (1 MB)
__device__ int   g_perm[EMAX];         // edge ids grouped by tgt (2 MB)
__device__ int   g_src[EMAX];          // src ids in the same order (2 MB)
__device__ int   g_mask_kind;          // 0=u8, 1=i32, 2=f32

// ---------------------------------------------------------------------------
// Kernel 0: classify tree_mask storage (first 4096 words safe for all dtypes)
// ---------------------------------------------------------------------------
__global__ void detect_mask_kind_kernel(const uint32_t* __restrict__ mw) {
    __shared__ int ok_i32, ok_f32;
    if (threadIdx.x == 0) { ok_i32 = 1; ok_f32 = 1; }
    __syncthreads();
    int li = 1, lf = 1;
    for (int i = threadIdx.x; i < 4096; i += blockDim.x) {
        uint32_t w = mw[i];
        if (!(w == 0u || w == 1u)) li = 0;
        if (!(w == 0u || w == 0x3F800000u)) lf = 0;
    }
    if (!li) ok_i32 = 0;   // benign race: all writers store 0
    if (!lf) ok_f32 = 0;
    __syncthreads();
    if (threadIdx.x == 0) g_mask_kind = ok_i32 ? 1 : (ok_f32 ? 2 : 0);
}

// ---------------------------------------------------------------------------
// Kernel 1: V[g][d] = sum_f W[d][f] * goal_type[g][f]
// ---------------------------------------------------------------------------
__global__ void compute_V_kernel(const float* __restrict__ goal,
                                 const float* __restrict__ W) {
    __shared__ float sg[32][Dc];           // 32 KB
    const int g0 = blockIdx.x * 32;
    for (int i = threadIdx.x; i < 32 * Dc; i += blockDim.x) {
        int g = i >> 8, f = i & 255;
        sg[g][f] = goal[(size_t)(g0 + g) * (Tc * Dc) + f];
    }
    __syncthreads();
    const int d = threadIdx.x;
    float acc[32];
#pragma unroll
    for (int g = 0; g < 32; g++) acc[g] = 0.f;
    const float4* Wrow = reinterpret_cast<const float4*>(W + (size_t)d * Dc);
#pragma unroll 4
    for (int f4 = 0; f4 < Dc / 4; f4++) {
        float4 w = Wrow[f4];
#pragma unroll
        for (int g = 0; g < 32; g++) {
            float4 s = reinterpret_cast<const float4*>(sg[g])[f4];  // broadcast
            acc[g] += w.x * s.x + w.y * s.y + w.z * s.z + w.w * s.w;
        }
    }
#pragma unroll
    for (int g = 0; g < 32; g++)
        g_V[(size_t)(g0 + g) * Dc + d] = acc[g];
}

// ---------------------------------------------------------------------------
// Bucketing pass A: per-block privatized histogram (smem atomics only).
// ---------------------------------------------------------------------------
__global__ void hist_local_kernel(const int* __restrict__ ei, int E, int CH) {
    __shared__ int h[NTGT];                 // 8 KB
    for (int i = threadIdx.x; i < NTGT; i += 256) h[i] = 0;
    __syncthreads();
    const int s = blockIdx.x * CH;
    const int e = (s + CH < E) ? s + CH : E;
    for (int i = s + threadIdx.x; i < e; i += 256)
        atomicAdd(&h[ei[E + i]], 1);
    __syncthreads();
    for (int i = threadIdx.x; i < NTGT; i += 256)
        g_mat[blockIdx.x * NTGT + i] = h[i];
}

// Pass B1: column-wise exclusive scan over blocks (coalesced, no atomics).
// thread t owns tgt t; g_mat[bi][t] becomes prefix, g_cnt[t] = total.
__global__ void col_scan_kernel() {
    const int t = blockIdx.x * blockDim.x + threadIdx.x;
    if (t >= NTGT) return;
    int run = 0;
#pragma unroll 4
    for (int bi = 0; bi < NB; bi++) {
        int v = g_mat[bi * NTGT + t];
        g_mat[bi * NTGT + t] = run;
        run += v;
    }
    g_cnt[t] = run;
}

// Pass B2: single block, exclusive scan of g_cnt -> g_base.
__global__ void scan_kernel() {
    __shared__ int wsum[32];
    const int t = threadIdx.x, lane = t & 31, w = t >> 5;
    int a = g_cnt[2 * t], b = g_cnt[2 * t + 1];
    int s = a + b;
    int v = s;
#pragma unroll
    for (int o = 1; o < 32; o <<= 1) {
        int u = __shfl_up_sync(0xffffffffu, v, o);
        if (lane >= o) v += u;
    }
    if (lane == 31) wsum[w] = v;
    __syncthreads();
    if (w == 0) {
        int x = wsum[lane];
#pragma unroll
        for (int o = 1; o < 32; o <<= 1) {
            int u = __shfl_up_sync(0xffffffffu, x, o);
            if (lane >= o) x += u;
        }
        wsum[lane] = x;
    }
    __syncthreads();
    int excl = v - s + (w ? wsum[w - 1] : 0);
    g_base[2 * t] = excl;
    g_base[2 * t + 1] = excl + a;
}

// Pass C: scatter with per-block smem offsets (absolute bases preloaded).
// Also records src so the edge kernel reads it coalesced.
__global__ void scatter2_kernel(const int* __restrict__ ei, int E, int CH) {
    __shared__ int off[NTGT];               // 8 KB
    for (int i = threadIdx.x; i < NTGT; i += 256)
        off[i] = g_base[i] + g_mat[blockIdx.x * NTGT + i];
    __syncthreads();
    const int s = blockIdx.x * CH;
    const int e = (s + CH < E) ? s + CH : E;
    for (int i = s + threadIdx.x; i < e; i += 256) {
        const int t = ei[E + i];
        const int p = atomicAdd(&off[t], 1);
        g_perm[p] = i;
        g_src[p] = ei[i];
    }
}

// ---------------------------------------------------------------------------
// Kernel 2: lemma_preds[e] = dot(scope_type[src[e]], V[tgt[e]]) + bias.
// One block per tgt bucket; V[tgt] held in registers (per-lane float4x2);
// warp-per-edge streams only the scope row (500 MB total LTS traffic).
// ---------------------------------------------------------------------------
__global__ void edge_grouped_kernel(const float* __restrict__ scope,
                                    const float* __restrict__ bias,
                                    float* __restrict__ out, int E) {
    __shared__ float sV[Dc];
    const int tgt = blockIdx.x;
    for (int i = threadIdx.x; i < Dc; i += blockDim.x)
        sV[i] = g_V[(size_t)tgt * Dc + i];
    __syncthreads();

    const int w = threadIdx.x >> 5, lane = threadIdx.x & 31;
    const float4* v4 = reinterpret_cast<const float4*>(sV);
    const float4 v0 = v4[lane], v1 = v4[lane + 32];
    const float b0 = __ldg(bias);
    const int base = g_base[tgt], cnt = g_cnt[tgt];

    for (int i = w; i < cnt; i += 8) {
        const int e   = g_perm[base + i];
        const int src = g_src[base + i];
        const float4* s = reinterpret_cast<const float4*>(scope + (size_t)src * (Tc * Dc));
        float4 s0 = s[lane], s1 = s[lane + 32];
        float p = s0.x * v0.x + s0.y * v0.y + s0.z * v0.z + s0.w * v0.w
                + s1.x * v1.x + s1.y * v1.y + s1.z * v1.z + s1.w * v1.w;
#pragma unroll
        for (int o = 16; o; o >>= 1) p += __shfl_xor_sync(0xffffffffu, p, o);
        if (lane == 0) out[e] = p + b0;
    }
}

// ---------------------------------------------------------------------------
// Kernel 3: lm_preds — shared-memory micro-GEMM, no inner-loop shuffles.
// ---------------------------------------------------------------------------
#define NT 32
#define MG 4
__global__ void lm_kernel2(const float* __restrict__ scope,
                           const int* __restrict__ lm_idx,
                           const int* __restrict__ bpts,
                           const void* __restrict__ tree_mask,
                           float* __restrict__ out, int M) {
    __shared__ float sS[Dc * NT];          // 32 KB, [d][n^sw(d)]
    __shared__ float sM[Dc * MG];          // 4 KB, [d][mi]
    __shared__ float sP[8 * MG * NT];      // 4 KB, [q][mi][n]
    __shared__ int   s_list[1024];         // a batch may own all of M
    __shared__ int   s_cnt;
    __shared__ unsigned s_tm;

    const int b = blockIdx.y;
    const int n0 = blockIdx.x * NT;
    const int tid = threadIdx.x, lane = tid & 31, q = tid >> 5;

    if (tid == 0) s_cnt = 0;
    __syncthreads();

    for (int m = tid; m < M; m += 256)
        if (bpts[m] == b) {
            int p = atomicAdd(&s_cnt, 1);
            s_list[p] = m;
        }

    if (q == 0) {
        const int n = n0 + lane;
        const int kind = g_mask_kind;
        bool mk;
        if (kind == 0)      mk = ((const uint8_t*)tree_mask)[b * Nc + n] != 0;
        else if (kind == 1) mk = ((const int*)tree_mask)[b * Nc + n] != 0;
        else                mk = ((const float*)tree_mask)[b * Nc + n] != 0.f;
        unsigned bal = __ballot_sync(0xffffffffu, mk);
        if (lane == 0) s_tm = bal;
    }

    // stage scope tile transposed + swizzled: (d,n) at [d*NT + (n^((d>>2)&31))]
    for (int idx = tid; idx < NT * (Dc / 4); idx += 256) {
        const int n = idx >> 6, d4 = idx & 63;
        float4 v = *reinterpret_cast<const float4*>(
            scope + (size_t)(b * Nc + n0 + n) * (Tc * Dc) + d4 * 4);
        const int d = d4 * 4;
        const int sw = d4 & 31;
        sS[(d + 0) * NT + (n ^ sw)] = v.x;
        sS[(d + 1) * NT + (n ^ sw)] = v.y;
        sS[(d + 2) * NT + (n ^ sw)] = v.z;
        sS[(d + 3) * NT + (n ^ sw)] = v.w;
    }
    __syncthreads();

    const int cnt = (s_cnt < M) ? s_cnt : M;
    const unsigned tmbits = s_tm;

    for (int i0 = 0; i0 < cnt; i0 += MG) {
        const int g = (cnt - i0 < MG) ? (cnt - i0) : MG;
        for (int idx = tid; idx < g * Dc; idx += 256) {
            const int mi = idx >> 8, d = idx & 255;
            sM[d * MG + mi] = scope[(size_t)lm_idx[s_list[i0 + mi]] * Dc + d];
        }
        __syncthreads();

        float acc0 = 0.f, acc1 = 0.f, acc2 = 0.f, acc3 = 0.f;
#pragma unroll
        for (int i = 0; i < 32; i++) {
            const int d = q * 32 + i;
            const float sval = sS[d * NT + (lane ^ ((d >> 2) & 31))];
            const float4 mv = *reinterpret_cast<const float4*>(sM + d * MG);
            acc0 += sval * mv.x;
            acc1 += sval * mv.y;
            acc2 += sval * mv.z;
            acc3 += sval * mv.w;
        }
        sP[(q * MG + 0) * NT + lane] = acc0;
        sP[(q * MG + 1) * NT + lane] = acc1;
        sP[(q * MG + 2) * NT + lane] = acc2;
        sP[(q * MG + 3) * NT + lane] = acc3;
        __syncthreads();

        if (tid < 32 * g) {
            const int n = lane, mi = q;
            float sum = 0.f;
#pragma unroll
            for (int qq = 0; qq < 8; qq++)
                sum += sP[(qq * MG + mi) * NT + n];
            const int m = s_list[i0 + mi];
            out[(size_t)m * Nc + n0 + n] = ((tmbits >> n) & 1u) ? sum : NEGV;
        }
        __syncthreads();
    }
}

// ---------------------------------------------------------------------------
// Launcher. Inputs: scope, goal, W, bias, edge_index, lm_mask_idx, batch_pts,
// tree_mask. Output: [lemma_preds (E) | lm_preds (M*Nc)] float32.
// ---------------------------------------------------------------------------
extern "C" void kernel_launch(void* const* d_in, const int* in_sizes, int n_in,
                              void* d_out, int out_size) {
    const float* scope = (const float*)d_in[0];
    const float* goal  = (const float*)d_in[1];
    const float* W     = (const float*)d_in[2];
    const float* bias  = (const float*)d_in[3];
    const int*   ei    = (const int*)d_in[4];
    const int*   lmidx = (const int*)d_in[5];
    const int*   bpts  = (const int*)d_in[6];
    const void*  tmask = d_in[7];
    float* out = (float*)d_out;

    const int E = in_sizes[4] / 2;
    const int M = in_sizes[5];
    const int CH = (E + NB - 1) / NB;

    detect_mask_kind_kernel<<<1, 256>>>((const uint32_t*)tmask);
    compute_V_kernel<<<(Bc * Gc) / 32, 256>>>(goal, W);

    hist_local_kernel<<<NB, 256>>>(ei, E, CH);
    col_scan_kernel<<<NTGT / 256, 256>>>();
    scan_kernel<<<1, 1024>>>();
    scatter2_kernel<<<NB, 256>>>(ei, E, CH);

    edge_grouped_kernel<<<NTGT, 256>>>(scope, bias, out, E);
    lm_kernel2<<<dim3(Nc / NT, Bc), 256>>>(scope, lmidx, bpts, tmask,
                                           out + E, M);
}

// round 7
// speedup vs baseline: 1.3282x; 1.0650x over previous
#include <cuda_runtime.h>
#include <stdint.h>

// Problem constants
#define Bc 32
#define Nc 512
#define Gc 64
#define Tc 16
#define Dc 256
#define NTGT (Bc * Gc)          // 2048 goal rows
#define EMAX 500000
#define NB 128                  // bucketing blocks

static __device__ __constant__ float NEGV = -1.0e10f;

// Scratch (static __device__ per harness rules)
__device__ float g_V[NTGT * Dc];       // V[g][d] = W @ goal_type[g]   (2 MB)
__device__ int   g_cnt[NTGT];
__device__ int   g_base[NTGT];
__device__ int   g_mat[NTGT * NB];     // TRANSPOSED: [tgt][block] counts->prefixes
__device__ int2  g_pair[EMAX];         // (edge id, src) grouped by tgt (4 MB)
__device__ int   g_mask_kind;          // 0=u8, 1=i32, 2=f32

// ---------------------------------------------------------------------------
// Kernel 0: classify tree_mask storage (first 4096 words safe for all dtypes)
// ---------------------------------------------------------------------------
__global__ void detect_mask_kind_kernel(const uint32_t* __restrict__ mw) {
    __shared__ int ok_i32, ok_f32;
    if (threadIdx.x == 0) { ok_i32 = 1; ok_f32 = 1; }
    __syncthreads();
    int li = 1, lf = 1;
    for (int i = threadIdx.x; i < 4096; i += blockDim.x) {
        uint32_t w = mw[i];
        if (!(w == 0u || w == 1u)) li = 0;
        if (!(w == 0u || w == 0x3F800000u)) lf = 0;
    }
    if (!li) ok_i32 = 0;   // benign race: all writers store 0
    if (!lf) ok_f32 = 0;
    __syncthreads();
    if (threadIdx.x == 0) g_mask_kind = ok_i32 ? 1 : (ok_f32 ? 2 : 0);
}

// ---------------------------------------------------------------------------
// Kernel 1: V[g][d] = sum_f W[d][f] * goal_type[g][f]
// ---------------------------------------------------------------------------
__global__ void compute_V_kernel(const float* __restrict__ goal,
                                 const float* __restrict__ W) {
    __shared__ float sg[32][Dc];           // 32 KB
    const int g0 = blockIdx.x * 32;
    for (int i = threadIdx.x; i < 32 * Dc; i += blockDim.x) {
        int g = i >> 8, f = i & 255;
        sg[g][f] = goal[(size_t)(g0 + g) * (Tc * Dc) + f];
    }
    __syncthreads();
    const int d = threadIdx.x;
    float acc[32];
#pragma unroll
    for (int g = 0; g < 32; g++) acc[g] = 0.f;
    const float4* Wrow = reinterpret_cast<const float4*>(W + (size_t)d * Dc);
#pragma unroll 4
    for (int f4 = 0; f4 < Dc / 4; f4++) {
        float4 w = Wrow[f4];
#pragma unroll
        for (int g = 0; g < 32; g++) {
            float4 s = reinterpret_cast<const float4*>(sg[g])[f4];  // broadcast
            acc[g] += w.x * s.x + w.y * s.y + w.z * s.z + w.w * s.w;
        }
    }
#pragma unroll
    for (int g = 0; g < 32; g++)
        g_V[(size_t)(g0 + g) * Dc + d] = acc[g];
}

// ---------------------------------------------------------------------------
// Bucketing pass A: per-block privatized histogram (smem atomics only),
// written TRANSPOSED: g_mat[t * NB + block].
// ---------------------------------------------------------------------------
__global__ void hist_local_kernel(const int* __restrict__ ei, int E, int CH) {
    __shared__ int h[NTGT];                 // 8 KB
    for (int i = threadIdx.x; i < NTGT; i += 256) h[i] = 0;
    __syncthreads();
    const int s = blockIdx.x * CH;
    const int e = (s + CH < E) ? s + CH : E;
    for (int i = s + threadIdx.x; i < e; i += 256)
        atomicAdd(&h[ei[E + i]], 1);
    __syncthreads();
    for (int i = threadIdx.x; i < NTGT; i += 256)
        g_mat[i * NB + blockIdx.x] = h[i];
}

// Pass B1: one WARP per tgt — int4 row load (4 counts/lane), in-lane prefix +
// warp exclusive scan. Fully parallel (2048 warps), no serial latency chain.
__global__ void col_scan_kernel() {
    const int t = (blockIdx.x * blockDim.x + threadIdx.x) >> 5;
    const int lane = threadIdx.x & 31;
    if (t >= NTGT) return;
    int4 v = reinterpret_cast<const int4*>(g_mat + t * NB)[lane];
    const int s0 = v.x, s1 = s0 + v.y, s2 = s1 + v.z, s3 = s2 + v.w;
    int run = s3;
#pragma unroll
    for (int o = 1; o < 32; o <<= 1) {
        int u = __shfl_up_sync(0xffffffffu, run, o);
        if (lane >= o) run += u;
    }
    const int excl = run - s3;
    int4 w = make_int4(excl, excl + s0, excl + s1, excl + s2);
    reinterpret_cast<int4*>(g_mat + t * NB)[lane] = w;
    if (lane == 31) g_cnt[t] = run;
}

// Pass B2: single block, exclusive scan of g_cnt -> g_base.
__global__ void scan_kernel() {
    __shared__ int wsum[32];
    const int t = threadIdx.x, lane = t & 31, w = t >> 5;
    int a = g_cnt[2 * t], b = g_cnt[2 * t + 1];
    int s = a + b;
    int v = s;
#pragma unroll
    for (int o = 1; o < 32; o <<= 1) {
        int u = __shfl_up_sync(0xffffffffu, v, o);
        if (lane >= o) v += u;
    }
    if (lane == 31) wsum[w] = v;
    __syncthreads();
    if (w == 0) {
        int x = wsum[lane];
#pragma unroll
        for (int o = 1; o < 32; o <<= 1) {
            int u = __shfl_up_sync(0xffffffffu, x, o);
            if (lane >= o) x += u;
        }
        wsum[lane] = x;
    }
    __syncthreads();
    int excl = v - s + (w ? wsum[w - 1] : 0);
    g_base[2 * t] = excl;
    g_base[2 * t + 1] = excl + a;
}

// Pass C: scatter with per-block smem offsets (absolute bases preloaded).
// (edge id, src) packed in one int2 -> single STG.64 per edge.
__global__ void scatter2_kernel(const int* __restrict__ ei, int E, int CH) {
    __shared__ int off[NTGT];               // 8 KB
    for (int i = threadIdx.x; i < NTGT; i += 256)
        off[i] = g_base[i] + g_mat[i * NB + blockIdx.x];
    __syncthreads();
    const int s = blockIdx.x * CH;
    const int e = (s + CH < E) ? s + CH : E;
    for (int i = s + threadIdx.x; i < e; i += 256) {
        const int t = ei[E + i];
        const int p = atomicAdd(&off[t], 1);
        g_pair[p] = make_int2(i, ei[i]);
    }
}

// ---------------------------------------------------------------------------
// Kernel 2: lemma_preds[e] = dot(scope_type[src[e]], V[tgt[e]]) + bias.
// One block per tgt bucket; V[tgt] held in registers (per-lane float4x2).
// 2 edges per warp-iteration to overlap the SHFL reduction chains.
// ---------------------------------------------------------------------------
__global__ void edge_grouped_kernel(const float* __restrict__ scope,
                                    const float* __restrict__ bias,
                                    float* __restrict__ out, int E) {
    __shared__ float sV[Dc];
    const int tgt = blockIdx.x;
    for (int i = threadIdx.x; i < Dc; i += blockDim.x)
        sV[i] = g_V[(size_t)tgt * Dc + i];
    __syncthreads();

    const int w = threadIdx.x >> 5, lane = threadIdx.x & 31;
    const float4* v4 = reinterpret_cast<const float4*>(sV);
    const float4 v0 = v4[lane], v1 = v4[lane + 32];
    const float b0 = __ldg(bias);
    const int base = g_base[tgt], cnt = g_cnt[tgt];

    int i = 2 * w;
    for (; i + 1 < cnt; i += 16) {
        const int2 pa = g_pair[base + i];
        const int2 pb = g_pair[base + i + 1];
        const float4* sa = reinterpret_cast<const float4*>(scope + (size_t)pa.y * (Tc * Dc));
        const float4* sb = reinterpret_cast<const float4*>(scope + (size_t)pb.y * (Tc * Dc));
        float4 a0 = sa[lane], a1 = sa[lane + 32];
        float4 b0v = sb[lane], b1v = sb[lane + 32];
        float pA = a0.x * v0.x + a0.y * v0.y + a0.z * v0.z + a0.w * v0.w
                 + a1.x * v1.x + a1.y * v1.y + a1.z * v1.z + a1.w * v1.w;
        float pB = b0v.x * v0.x + b0v.y * v0.y + b0v.z * v0.z + b0v.w * v0.w
                 + b1v.x * v1.x + b1v.y * v1.y + b1v.z * v1.z + b1v.w * v1.w;
#pragma unroll
        for (int o = 16; o; o >>= 1) {
            pA += __shfl_xor_sync(0xffffffffu, pA, o);
            pB += __shfl_xor_sync(0xffffffffu, pB, o);
        }
        if (lane == 0) { out[pa.x] = pA + b0; out[pb.x] = pB + b0; }
    }
    if (i < cnt) {
        const int2 pa = g_pair[base + i];
        const float4* sa = reinterpret_cast<const float4*>(scope + (size_t)pa.y * (Tc * Dc));
        float4 a0 = sa[lane], a1 = sa[lane + 32];
        float pA = a0.x * v0.x + a0.y * v0.y + a0.z * v0.z + a0.w * v0.w
                 + a1.x * v1.x + a1.y * v1.y + a1.z * v1.z + a1.w * v1.w;
#pragma unroll
        for (int o = 16; o; o >>= 1) pA += __shfl_xor_sync(0xffffffffu, pA, o);
        if (lane == 0) out[pa.x] = pA + b0;
    }
}

// ---------------------------------------------------------------------------
// Kernel 3: lm_preds — shared-memory micro-GEMM, no inner-loop shuffles.
// ---------------------------------------------------------------------------
#define NT 32
#define MG 4
__global__ void lm_kernel2(const float* __restrict__ scope,
                           const int* __restrict__ lm_idx,
                           const int* __restrict__ bpts,
                           const void* __restrict__ tree_mask,
                           float* __restrict__ out, int M) {
    __shared__ float sS[Dc * NT];          // 32 KB, [d][n^sw(d)]
    __shared__ float sM[Dc * MG];          // 4 KB, [d][mi]
    __shared__ float sP[8 * MG * NT];      // 4 KB, [q][mi][n]
    __shared__ int   s_list[1024];         // a batch may own all of M
    __shared__ int   s_cnt;
    __shared__ unsigned s_tm;

    const int b = blockIdx.y;
    const int n0 = blockIdx.x * NT;
    const int tid = threadIdx.x, lane = tid & 31, q = tid >> 5;

    if (tid == 0) s_cnt = 0;
    __syncthreads();

    for (int m = tid; m < M; m += 256)
        if (bpts[m] == b) {
            int p = atomicAdd(&s_cnt, 1);
            s_list[p] = m;
        }

    if (q == 0) {
        const int n = n0 + lane;
        const int kind = g_mask_kind;
        bool mk;
        if (kind == 0)      mk = ((const uint8_t*)tree_mask)[b * Nc + n] != 0;
        else if (kind == 1) mk = ((const int*)tree_mask)[b * Nc + n] != 0;
        else                mk = ((const float*)tree_mask)[b * Nc + n] != 0.f;
        unsigned bal = __ballot_sync(0xffffffffu, mk);
        if (lane == 0) s_tm = bal;
    }

    // stage scope tile transposed + swizzled: (d,n) at [d*NT + (n^((d>>2)&31))]
    for (int idx = tid; idx < NT * (Dc / 4); idx += 256) {
        const int n = idx >> 6, d4 = idx & 63;
        float4 v = *reinterpret_cast<const float4*>(
            scope + (size_t)(b * Nc + n0 + n) * (Tc * Dc) + d4 * 4);
        const int d = d4 * 4;
        const int sw = d4 & 31;
        sS[(d + 0) * NT + (n ^ sw)] = v.x;
        sS[(d + 1) * NT + (n ^ sw)] = v.y;
        sS[(d + 2) * NT + (n ^ sw)] = v.z;
        sS[(d + 3) * NT + (n ^ sw)] = v.w;
    }
    __syncthreads();

    const int cnt = (s_cnt < M) ? s_cnt : M;
    const unsigned tmbits = s_tm;

    for (int i0 = 0; i0 < cnt; i0 += MG) {
        const int g = (cnt - i0 < MG) ? (cnt - i0) : MG;
        for (int idx = tid; idx < g * Dc; idx += 256) {
            const int mi = idx >> 8, d = idx & 255;
            sM[d * MG + mi] = scope[(size_t)lm_idx[s_list[i0 + mi]] * Dc + d];
        }
        __syncthreads();

        float acc0 = 0.f, acc1 = 0.f, acc2 = 0.f, acc3 = 0.f;
#pragma unroll
        for (int i = 0; i < 32; i++) {
            const int d = q * 32 + i;
            const float sval = sS[d * NT + (lane ^ ((d >> 2) & 31))];
            const float4 mv = *reinterpret_cast<const float4*>(sM + d * MG);
            acc0 += sval * mv.x;
            acc1 += sval * mv.y;
            acc2 += sval * mv.z;
            acc3 += sval * mv.w;
        }
        sP[(q * MG + 0) * NT + lane] = acc0;
        sP[(q * MG + 1) * NT + lane] = acc1;
        sP[(q * MG + 2) * NT + lane] = acc2;
        sP[(q * MG + 3) * NT + lane] = acc3;
        __syncthreads();

        if (tid < 32 * g) {
            const int n = lane, mi = q;
            float sum = 0.f;
#pragma unroll
            for (int qq = 0; qq < 8; qq++)
                sum += sP[(qq * MG + mi) * NT + n];
            const int m = s_list[i0 + mi];
            out[(size_t)m * Nc + n0 + n] = ((tmbits >> n) & 1u) ? sum : NEGV;
        }
        __syncthreads();
    }
}

// ---------------------------------------------------------------------------
// Launcher. Inputs: scope, goal, W, bias, edge_index, lm_mask_idx, batch_pts,
// tree_mask. Output: [lemma_preds (E) | lm_preds (M*Nc)] float32.
// ---------------------------------------------------------------------------
extern "C" void kernel_launch(void* const* d_in, const int* in_sizes, int n_in,
                              void* d_out, int out_size) {
    const float* scope = (const float*)d_in[0];
    const float* goal  = (const float*)d_in[1];
    const float* W     = (const float*)d_in[2];
    const float* bias  = (const float*)d_in[3];
    const int*   ei    = (const int*)d_in[4];
    const int*   lmidx = (const int*)d_in[5];
    const int*   bpts  = (const int*)d_in[6];
    const void*  tmask = d_in[7];
    float* out = (float*)d_out;

    const int E = in_sizes[4] / 2;
    const int M = in_sizes[5];
    const int CH = (E + NB - 1) / NB;

    detect_mask_kind_kernel<<<1, 256>>>((const uint32_t*)tmask);
    compute_V_kernel<<<(Bc * Gc) / 32, 256>>>(goal, W);

    hist_local_kernel<<<NB, 256>>>(ei, E, CH);
    col_scan_kernel<<<NTGT * 32 / 256, 256>>>();
    scan_kernel<<<1, 1024>>>();
    scatter2_kernel<<<NB, 256>>>(ei, E, CH);

    edge_grouped_kernel<<<NTGT, 256>>>(scope, bias, out, E);
    lm_kernel2<<<dim3(Nc / NT, Bc), 256>>>(scope, lmidx, bpts, tmask,
                                           out + E, M);
}